// round 14
// baseline (speedup 1.0000x reference)
#include <cuda_runtime.h>
#include <cuda_bf16.h>
#include <cstdint>
#include <cstddef>
#include <math.h>

// Problem constants
#define B_  2
#define S_  2048
#define D_  1024
#define H_  16
#define HD_ 64
#define MROWS 4096
#define QKV_N 3072
#define KBASE 1024
#define KW   2048          // [hi | lo] operand width

// ---------------------------------------------------------------------------
// Device-global scratch (allocation-free)
// ---------------------------------------------------------------------------
__device__ __nv_bfloat16 g_Xp   [(size_t)MROWS * KW];        // X2     [4096,2048]
__device__ __nv_bfloat16 g_Wqkvp[(size_t)QKV_N * KW];        // Wqkv2  [3072,2048]
__device__ __nv_bfloat16 g_attnp[(size_t)MROWS * KW];        // attn2  [4096,2048]
__device__ __nv_bfloat16 g_Woutp[(size_t)D_    * KW];        // Wout2  [1024,2048]
__device__ __nv_bfloat16 g_Qp[(size_t)B_ * H_ * S_ * 128];   // [b,h,s,(hi|lo)]
__device__ __nv_bfloat16 g_Kp[(size_t)B_ * H_ * S_ * 128];
__device__ __nv_bfloat16 g_Vp[(size_t)B_ * H_ * S_ * 128];

// ---------------------------------------------------------------------------
// Helpers
// ---------------------------------------------------------------------------
__device__ __forceinline__ uint32_t s2u(const void* p) {
    uint32_t a;
    asm("{ .reg .u64 t; cvta.to.shared.u64 t, %1; cvt.u32.u64 %0, t; }"
        : "=r"(a) : "l"(p));
    return a;
}
__device__ __forceinline__ void ldmatrix_x4(uint32_t* r, uint32_t addr) {
    asm volatile("ldmatrix.sync.aligned.m8n8.x4.shared.b16 {%0,%1,%2,%3}, [%4];"
                 : "=r"(r[0]), "=r"(r[1]), "=r"(r[2]), "=r"(r[3]) : "r"(addr));
}
__device__ __forceinline__ void ldmatrix_x4_t(uint32_t* r, uint32_t addr) {
    asm volatile("ldmatrix.sync.aligned.m8n8.x4.trans.shared.b16 {%0,%1,%2,%3}, [%4];"
                 : "=r"(r[0]), "=r"(r[1]), "=r"(r[2]), "=r"(r[3]) : "r"(addr));
}
__device__ __forceinline__ void mma16816(float* c, const uint32_t* a,
                                         const uint32_t* b) {
    asm volatile(
        "mma.sync.aligned.m16n8k16.row.col.f32.bf16.bf16.f32 "
        "{%0,%1,%2,%3}, {%4,%5,%6,%7}, {%8,%9}, {%0,%1,%2,%3};"
        : "+f"(c[0]), "+f"(c[1]), "+f"(c[2]), "+f"(c[3])
        : "r"(a[0]), "r"(a[1]), "r"(a[2]), "r"(a[3]), "r"(b[0]), "r"(b[1]));
}
__device__ __forceinline__ void cp_async16(uint32_t dst, const void* src) {
    asm volatile("cp.async.cg.shared.global [%0], [%1], 16;" :: "r"(dst), "l"(src));
}
__device__ __forceinline__ uint32_t pack_bf2(float lo, float hi) {
    uint32_t d;
    asm("cvt.rn.bf16x2.f32 %0, %1, %2;" : "=r"(d) : "f"(hi), "f"(lo));
    return d;
}

// ---------------------------------------------------------------------------
// fp32 -> bf16 [hi | lo] split, vectorized x4. dst row = [hi(K) | lo(K)]
// ---------------------------------------------------------------------------
__global__ void __launch_bounds__(256)
convert_split4(const float4* __restrict__ src, __nv_bfloat16* __restrict__ dst,
               int K, int total4)
{
    int i4 = blockIdx.x * 256 + threadIdx.x;
    if (i4 >= total4) return;
    int idx = i4 * 4;
    int m = idx / K, k = idx - m * K;
    float4 x = src[i4];
    uint32_t hh0 = pack_bf2(x.x, x.y);
    uint32_t hh1 = pack_bf2(x.z, x.w);
    __nv_bfloat162 h0 = *(__nv_bfloat162*)&hh0;
    __nv_bfloat162 h1 = *(__nv_bfloat162*)&hh1;
    uint32_t ll0 = pack_bf2(x.x - __bfloat162float(h0.x),
                            x.y - __bfloat162float(h0.y));
    uint32_t ll1 = pack_bf2(x.z - __bfloat162float(h1.x),
                            x.w - __bfloat162float(h1.y));
    size_t base = (size_t)m * (2 * K) + k;
    *(uint2*)&dst[base]     = make_uint2(hh0, hh1);
    *(uint2*)&dst[base + K] = make_uint2(ll0, ll1);
}

// ---------------------------------------------------------------------------
// Fused error-compensated GEMM over K=1024 with [hi|lo] operands:
//   C = Ahi.Bhi^T + Ahi.Blo^T + Alo.Bhi^T   (fp32 accum)
// CTA 128x128, 4 warps (64x64 warp tile), K-chunk 16, 3-stage cp.async,
// ONE barrier per chunk, 2 CTAs/SM.
// Term loop HOISTED: consecutive MMAs touch 32 distinct accumulators
// (RAW distance 32 instead of 1).
// ---------------------------------------------------------------------------
#define BM 128
#define BN 128
#define BKC 16
#define GPAD 24                                  // 16 data + 8 pad bf16
#define STAGE_BYTES (512 * GPAD * 2)             // 24576
#define GEMM_SMEM   (3 * STAGE_BYTES)            // 73728
#define GEMM_THREADS 128

struct GemmCtx {
    float acc[4][8][4];
    int mrow, ncol;
};

__device__ __forceinline__ void gemm_fused_prefetch(
    const __nv_bfloat16* __restrict__ A2, const __nv_bfloat16* __restrict__ B2,
    uint32_t sb, int koff, int tid)
{
    #pragma unroll
    for (int i = 0; i < 8; i++) {
        int g    = tid + i * GEMM_THREADS;   // 0..1023
        int row  = g >> 1;                   // 0..511
        int c8   = (g & 1) * 8;
        int part = row >> 7;                 // 0 Ahi, 1 Alo, 2 Bhi, 3 Blo
        int r    = row & 127;
        const __nv_bfloat16* base = (part < 2) ? A2 : B2;
        const __nv_bfloat16* src =
            base + (size_t)r * KW + (size_t)(part & 1) * KBASE + koff + c8;
        cp_async16(sb + (uint32_t)(row * GPAD + c8) * 2, src);
    }
}

__device__ __forceinline__ void gemm_core(
    const __nv_bfloat16* __restrict__ A2, const __nv_bfloat16* __restrict__ B2,
    int m0, int n0, uint32_t sbase, GemmCtx& ctx)
{
    const int tid  = threadIdx.x;
    const int wid  = tid >> 5;
    const int lane = tid & 31;
    const int wm   = wid & 1;
    const int wn   = wid >> 1;

    uint32_t ah_off[4], al_off[4], bh_off[4], bl_off[4];
    #pragma unroll
    for (int mi = 0; mi < 4; mi++) {
        int row = wm * 64 + mi * 16 + (lane & 15);
        int kk  = (lane >> 4) * 8;
        ah_off[mi] = (uint32_t)(row * GPAD + kk) * 2;
        al_off[mi] = (uint32_t)((128 + row) * GPAD + kk) * 2;
    }
    #pragma unroll
    for (int np = 0; np < 4; np++) {
        int row = wn * 64 + np * 16 + ((lane >> 4) << 3) + (lane & 7);
        int kk  = ((lane >> 3) & 1) * 8;
        bh_off[np] = (uint32_t)((256 + row) * GPAD + kk) * 2;
        bl_off[np] = (uint32_t)((384 + row) * GPAD + kk) * 2;
    }

    const __nv_bfloat16* Abase = A2 + (size_t)m0 * KW;
    const __nv_bfloat16* Bbase = B2 + (size_t)n0 * KW;

    #pragma unroll
    for (int i = 0; i < 4; i++)
        #pragma unroll
        for (int j = 0; j < 8; j++)
            #pragma unroll
            for (int x = 0; x < 4; x++) ctx.acc[i][j][x] = 0.f;

    const int NC = KBASE / BKC;   // 64

    gemm_fused_prefetch(Abase, Bbase, sbase, 0, tid);
    asm volatile("cp.async.commit_group;" ::: "memory");
    gemm_fused_prefetch(Abase, Bbase, sbase + STAGE_BYTES, BKC, tid);
    asm volatile("cp.async.commit_group;" ::: "memory");

    int slot = 0;
    for (int c = 0; c < NC; c++) {
        if (c + 1 < NC) {
            asm volatile("cp.async.wait_group 1;" ::: "memory");
        } else {
            asm volatile("cp.async.wait_group 0;" ::: "memory");
        }
        __syncthreads();

        if (c + 2 < NC) {
            int ps = slot + 2; if (ps >= 3) ps -= 3;
            gemm_fused_prefetch(Abase, Bbase,
                                sbase + (uint32_t)ps * STAGE_BYTES,
                                (c + 2) * BKC, tid);
            asm volatile("cp.async.commit_group;" ::: "memory");
        }

        const uint32_t scur = sbase + (uint32_t)slot * STAGE_BYTES;
        uint32_t ah[4][4], al[4][4];
        #pragma unroll
        for (int mi = 0; mi < 4; mi++) {
            ldmatrix_x4(ah[mi], scur + ah_off[mi]);
            ldmatrix_x4(al[mi], scur + al_off[mi]);
        }
        uint32_t bh[8][2], bl[8][2];
        #pragma unroll
        for (int np = 0; np < 4; np++) {
            uint32_t r[4];
            ldmatrix_x4(r, scur + bh_off[np]);
            bh[np * 2 + 0][0] = r[0]; bh[np * 2 + 0][1] = r[1];
            bh[np * 2 + 1][0] = r[2]; bh[np * 2 + 1][1] = r[3];
            ldmatrix_x4(r, scur + bl_off[np]);
            bl[np * 2 + 0][0] = r[0]; bl[np * 2 + 0][1] = r[1];
            bl[np * 2 + 1][0] = r[2]; bl[np * 2 + 1][1] = r[3];
        }
        // Term loop hoisted: each acc reused only after 31 other MMAs
        #pragma unroll
        for (int mi = 0; mi < 4; mi++)
            #pragma unroll
            for (int ni = 0; ni < 8; ni++)
                mma16816(ctx.acc[mi][ni], ah[mi], bh[ni]);  // hi.hi
        #pragma unroll
        for (int mi = 0; mi < 4; mi++)
            #pragma unroll
            for (int ni = 0; ni < 8; ni++)
                mma16816(ctx.acc[mi][ni], ah[mi], bl[ni]);  // hi.lo
        #pragma unroll
        for (int mi = 0; mi < 4; mi++)
            #pragma unroll
            for (int ni = 0; ni < 8; ni++)
                mma16816(ctx.acc[mi][ni], al[mi], bh[ni]);  // lo.hi
        if (++slot == 3) slot = 0;
    }
    ctx.mrow = m0 + wm * 64 + (lane >> 2);
    ctx.ncol = n0 + wn * 64 + (lane & 3) * 2;
}

__global__ void __launch_bounds__(GEMM_THREADS, 2)
gemm_mma(const __nv_bfloat16* __restrict__ A2, const __nv_bfloat16* __restrict__ B2,
         const float* __restrict__ bias, float* __restrict__ C, int N)
{
    extern __shared__ __align__(16) __nv_bfloat16 gsm[];
    GemmCtx ctx;
    gemm_core(A2, B2, blockIdx.y * BM, blockIdx.x * BN, s2u(gsm), ctx);
    #pragma unroll
    for (int mi = 0; mi < 4; mi++) {
        #pragma unroll
        for (int ni = 0; ni < 8; ni++) {
            int n = ctx.ncol + ni * 8;
            float b0 = bias[n], b1 = bias[n + 1];
            int mA = ctx.mrow + mi * 16;
            float2 v0 = make_float2(ctx.acc[mi][ni][0] + b0, ctx.acc[mi][ni][1] + b1);
            float2 v1 = make_float2(ctx.acc[mi][ni][2] + b0, ctx.acc[mi][ni][3] + b1);
            *(float2*)&C[(size_t)mA * N + n]       = v0;
            *(float2*)&C[(size_t)(mA + 8) * N + n] = v1;
        }
    }
}

__device__ __forceinline__ void qkv_store(float v0, float v1, int m, int n,
                                          const float* bias) {
    v0 += bias[n]; v1 += bias[n + 1];
    int sel = n >> 10, rem = n & 1023;
    int h = rem >> 6, d = rem & 63;
    if (sel == 0) { v0 *= 0.125f; v1 *= 0.125f; }
    __nv_bfloat16* dst = (sel == 0) ? g_Qp : (sel == 1) ? g_Kp : g_Vp;
    int b = m >> 11, s = m & 2047;
    size_t idx = (((size_t)(b * H_ + h)) * S_ + s) * 128 + d;
    __nv_bfloat16 h0 = __float2bfloat16(v0), h1 = __float2bfloat16(v1);
    __nv_bfloat16 l0 = __float2bfloat16(v0 - __bfloat162float(h0));
    __nv_bfloat16 l1 = __float2bfloat16(v1 - __bfloat162float(h1));
    __nv_bfloat162 hh; hh.x = h0; hh.y = h1;
    __nv_bfloat162 ll; ll.x = l0; ll.y = l1;
    *(__nv_bfloat162*)(dst + idx)      = hh;
    *(__nv_bfloat162*)(dst + idx + 64) = ll;
}

__global__ void __launch_bounds__(GEMM_THREADS, 2)
gemm_qkv(const __nv_bfloat16* __restrict__ A2, const __nv_bfloat16* __restrict__ B2,
         const float* __restrict__ bias)
{
    extern __shared__ __align__(16) __nv_bfloat16 gsm[];
    GemmCtx ctx;
    gemm_core(A2, B2, blockIdx.y * BM, blockIdx.x * BN, s2u(gsm), ctx);
    #pragma unroll
    for (int mi = 0; mi < 4; mi++) {
        #pragma unroll
        for (int ni = 0; ni < 8; ni++) {
            int n  = ctx.ncol + ni * 8;
            int mA = ctx.mrow + mi * 16;
            qkv_store(ctx.acc[mi][ni][0], ctx.acc[mi][ni][1], mA,     n, bias);
            qkv_store(ctx.acc[mi][ni][2], ctx.acc[mi][ni][3], mA + 8, n, bias);
        }
    }
}

// ---------------------------------------------------------------------------
// Tensor-core causal flash attention: 4 warps, 64 queries/CTA (16/warp),
// KV tiles of 64 keys, cp.async double-buffered, heavy blocks first.
// K-hi fragments loaded once for qhi AND qlo chains.
// P.V terms de-chained (three separate nt sweeps).
// Epilogue writes [hi|lo] attn2 rows (width 2048).
// ---------------------------------------------------------------------------
#define FA_PAD 136
#define FA_TILE_E (64 * FA_PAD)
#define FA_BUF_BYTES (2 * FA_TILE_E * 2)
#define FA_SMEM_TOTAL (2 * FA_BUF_BYTES)

__device__ __forceinline__ void fa_prefetch(uint32_t kdst, uint32_t vdst,
                                            const __nv_bfloat16* kg,
                                            const __nv_bfloat16* vg,
                                            int kt, int tid)
{
    #pragma unroll
    for (int i = 0; i < 8; i++) {
        int g = tid + i * 128;
        int r = g >> 4;
        int c = (g & 15) * 8;
        uint32_t so = (uint32_t)(r * FA_PAD + c) * 2;
        cp_async16(kdst + so, kg + (size_t)(kt + r) * 128 + c);
        cp_async16(vdst + so, vg + (size_t)(kt + r) * 128 + c);
    }
}

__global__ void __launch_bounds__(128)
fa_kernel(__nv_bfloat16* __restrict__ attnp)
{
    extern __shared__ __align__(16) __nv_bfloat16 dsm[];

    const int tid  = threadIdx.x;
    const int w    = tid >> 5;
    const int lane = tid & 31;
    const int blk  = (int)gridDim.x - 1 - (int)blockIdx.x;  // heavy first
    const int h    = blockIdx.y;
    const int b    = blockIdx.z;

    const size_t bh = ((size_t)b * H_ + h) * S_;
    const __nv_bfloat16* qg = g_Qp + (bh + (size_t)blk * 64) * 128;
    const __nv_bfloat16* kg = g_Kp + bh * 128;
    const __nv_bfloat16* vg = g_Vp + bh * 128;
    const uint32_t sbase = s2u(dsm);

    for (int i = tid; i < 64 * 16; i += 128) {
        int r = i >> 4, c = (i & 15) * 8;
        *(uint4*)(dsm + r * FA_PAD + c) = *(const uint4*)(qg + r * 128 + c);
    }
    __syncthreads();
    uint32_t qa[8][4];
    {
        uint32_t base = sbase +
            (uint32_t)(((w * 16 + (lane & 15)) * FA_PAD + (lane >> 4) * 8) * 2);
        #pragma unroll
        for (int g = 0; g < 8; g++) ldmatrix_x4(qa[g], base + g * 32);
    }
    __syncthreads();

    float oa[8][4];
    #pragma unroll
    for (int i = 0; i < 8; i++)
        #pragma unroll
        for (int j = 0; j < 4; j++) oa[i][j] = 0.f;
    float m0 = -INFINITY, m1 = -INFINITY, l0 = 0.f, l1 = 0.f;

    const int qrow0  = blk * 64 + w * 16;
    const int ntiles = blk + 1;

    const uint32_t brow  = ((lane >> 4) << 3) + (lane & 7);
    const uint32_t bksel = ((lane >> 3) & 1) * 8;
    const uint32_t vrow  = ((lane >> 3) & 1) * 8 + (lane & 7);
    const uint32_t vcol  = (lane >> 4) << 3;

    fa_prefetch(sbase, sbase + FA_TILE_E * 2, kg, vg, 0, tid);
    asm volatile("cp.async.commit_group;" ::: "memory");

    for (int t = 0; t < ntiles; t++) {
        const int buf = t & 1;
        const uint32_t sKa = sbase + (uint32_t)buf * FA_BUF_BYTES;
        const uint32_t sVa = sKa + FA_TILE_E * 2;

        if (t + 1 < ntiles) {
            const uint32_t nK = sbase + (uint32_t)(buf ^ 1) * FA_BUF_BYTES;
            fa_prefetch(nK, nK + FA_TILE_E * 2, kg, vg, (t + 1) * 64, tid);
            asm volatile("cp.async.commit_group;" ::: "memory");
            asm volatile("cp.async.wait_group 1;" ::: "memory");
        } else {
            asm volatile("cp.async.wait_group 0;" ::: "memory");
        }
        __syncthreads();

        float sa[8][4];
        #pragma unroll
        for (int i = 0; i < 8; i++)
            #pragma unroll
            for (int j = 0; j < 4; j++) sa[i][j] = 0.f;

        #pragma unroll
        for (int g = 0; g < 4; g++) {
            const uint32_t kc = (uint32_t)g * 16u;
            uint32_t bf[8][2];
            #pragma unroll
            for (int np = 0; np < 4; np++) {
                uint32_t r[4];
                ldmatrix_x4(r, sKa + (uint32_t)(((np * 16 + brow) * FA_PAD) + kc + bksel) * 2);
                bf[np * 2 + 0][0] = r[0]; bf[np * 2 + 0][1] = r[1];
                bf[np * 2 + 1][0] = r[2]; bf[np * 2 + 1][1] = r[3];
            }
            #pragma unroll
            for (int nt = 0; nt < 8; nt++)
                mma16816(sa[nt], qa[g], bf[nt]);
            #pragma unroll
            for (int nt = 0; nt < 8; nt++)
                mma16816(sa[nt], qa[4 + g], bf[nt]);
        }
        #pragma unroll
        for (int g = 0; g < 4; g++) {
            const uint32_t kc = 64u + (uint32_t)g * 16u;
            uint32_t bf[8][2];
            #pragma unroll
            for (int np = 0; np < 4; np++) {
                uint32_t r[4];
                ldmatrix_x4(r, sKa + (uint32_t)(((np * 16 + brow) * FA_PAD) + kc + bksel) * 2);
                bf[np * 2 + 0][0] = r[0]; bf[np * 2 + 0][1] = r[1];
                bf[np * 2 + 1][0] = r[2]; bf[np * 2 + 1][1] = r[3];
            }
            #pragma unroll
            for (int nt = 0; nt < 8; nt++)
                mma16816(sa[nt], qa[g], bf[nt]);
        }

        if (t == ntiles - 1) {
            const int kt = t * 64;
            const int r0 = qrow0 + (lane >> 2);
            const int r1 = r0 + 8;
            #pragma unroll
            for (int nt = 0; nt < 8; nt++) {
                int c0 = kt + nt * 8 + (lane & 3) * 2;
                if (c0     > r0) sa[nt][0] = -INFINITY;
                if (c0 + 1 > r0) sa[nt][1] = -INFINITY;
                if (c0     > r1) sa[nt][2] = -INFINITY;
                if (c0 + 1 > r1) sa[nt][3] = -INFINITY;
            }
        }

        float mx0 = -INFINITY, mx1 = -INFINITY;
        #pragma unroll
        for (int nt = 0; nt < 8; nt++) {
            mx0 = fmaxf(mx0, fmaxf(sa[nt][0], sa[nt][1]));
            mx1 = fmaxf(mx1, fmaxf(sa[nt][2], sa[nt][3]));
        }
        mx0 = fmaxf(mx0, __shfl_xor_sync(0xffffffff, mx0, 1));
        mx0 = fmaxf(mx0, __shfl_xor_sync(0xffffffff, mx0, 2));
        mx1 = fmaxf(mx1, __shfl_xor_sync(0xffffffff, mx1, 1));
        mx1 = fmaxf(mx1, __shfl_xor_sync(0xffffffff, mx1, 2));
        const float m0n = fmaxf(m0, mx0);
        const float m1n = fmaxf(m1, mx1);
        const float al0 = __expf(m0 - m0n);
        const float al1 = __expf(m1 - m1n);
        m0 = m0n; m1 = m1n;

        float rs0 = 0.f, rs1 = 0.f;
        uint32_t ph[4][4], pl[4][4];
        #pragma unroll
        for (int g = 0; g < 4; g++) {
            float p00 = __expf(sa[2*g][0] - m0),   p01 = __expf(sa[2*g][1] - m0);
            float p10 = __expf(sa[2*g][2] - m1),   p11 = __expf(sa[2*g][3] - m1);
            float q00 = __expf(sa[2*g+1][0] - m0), q01 = __expf(sa[2*g+1][1] - m0);
            float q10 = __expf(sa[2*g+1][2] - m1), q11 = __expf(sa[2*g+1][3] - m1);
            rs0 += p00 + p01 + q00 + q01;
            rs1 += p10 + p11 + q10 + q11;
            ph[g][0] = pack_bf2(p00, p01);
            ph[g][1] = pack_bf2(p10, p11);
            ph[g][2] = pack_bf2(q00, q01);
            ph[g][3] = pack_bf2(q10, q11);
            float f00 = p00 - __bfloat162float(__float2bfloat16(p00));
            float f01 = p01 - __bfloat162float(__float2bfloat16(p01));
            float f10 = p10 - __bfloat162float(__float2bfloat16(p10));
            float f11 = p11 - __bfloat162float(__float2bfloat16(p11));
            float g00 = q00 - __bfloat162float(__float2bfloat16(q00));
            float g01 = q01 - __bfloat162float(__float2bfloat16(q01));
            float g10 = q10 - __bfloat162float(__float2bfloat16(q10));
            float g11 = q11 - __bfloat162float(__float2bfloat16(q11));
            pl[g][0] = pack_bf2(f00, f01);
            pl[g][1] = pack_bf2(f10, f11);
            pl[g][2] = pack_bf2(g00, g01);
            pl[g][3] = pack_bf2(g10, g11);
        }
        rs0 += __shfl_xor_sync(0xffffffff, rs0, 1);
        rs0 += __shfl_xor_sync(0xffffffff, rs0, 2);
        rs1 += __shfl_xor_sync(0xffffffff, rs1, 1);
        rs1 += __shfl_xor_sync(0xffffffff, rs1, 2);
        l0 = l0 * al0 + rs0;
        l1 = l1 * al1 + rs1;
        #pragma unroll
        for (int nt = 0; nt < 8; nt++) {
            oa[nt][0] *= al0; oa[nt][1] *= al0;
            oa[nt][2] *= al1; oa[nt][3] *= al1;
        }

        #pragma unroll
        for (int g = 0; g < 4; g++) {
            uint32_t vh[8][2], vl[8][2];
            #pragma unroll
            for (int np = 0; np < 4; np++) {
                uint32_t r[4];
                uint32_t rowa = (uint32_t)((g * 16 + vrow) * FA_PAD) * 2;
                ldmatrix_x4_t(r, sVa + rowa + (uint32_t)(np * 16 + vcol) * 2);
                vh[np * 2 + 0][0] = r[0]; vh[np * 2 + 0][1] = r[1];
                vh[np * 2 + 1][0] = r[2]; vh[np * 2 + 1][1] = r[3];
                ldmatrix_x4_t(r, sVa + rowa + (uint32_t)(64 + np * 16 + vcol) * 2);
                vl[np * 2 + 0][0] = r[0]; vl[np * 2 + 0][1] = r[1];
                vl[np * 2 + 1][0] = r[2]; vl[np * 2 + 1][1] = r[3];
            }
            // de-chained: three separate nt sweeps (RAW distance 8)
            #pragma unroll
            for (int nt = 0; nt < 8; nt++)
                mma16816(oa[nt], ph[g], vh[nt]);
            #pragma unroll
            for (int nt = 0; nt < 8; nt++)
                mma16816(oa[nt], pl[g], vh[nt]);
            #pragma unroll
            for (int nt = 0; nt < 8; nt++)
                mma16816(oa[nt], ph[g], vl[nt]);
        }
        __syncthreads();
    }

    const float inv0 = 1.f / l0;
    const float inv1 = 1.f / l1;
    const int s0 = qrow0 + (lane >> 2);
    __nv_bfloat16* row0 = attnp + ((size_t)b * S_ + s0) * KW + h * 64;
    __nv_bfloat16* row1 = row0 + (size_t)8 * KW;
    #pragma unroll
    for (int nt = 0; nt < 8; nt++) {
        int d = nt * 8 + (lane & 3) * 2;
        float v00 = oa[nt][0] * inv0, v01 = oa[nt][1] * inv0;
        float v10 = oa[nt][2] * inv1, v11 = oa[nt][3] * inv1;
        __nv_bfloat16 h00 = __float2bfloat16(v00), h01 = __float2bfloat16(v01);
        __nv_bfloat16 h10 = __float2bfloat16(v10), h11 = __float2bfloat16(v11);
        __nv_bfloat162 hh0; hh0.x = h00; hh0.y = h01;
        __nv_bfloat162 hh1; hh1.x = h10; hh1.y = h11;
        __nv_bfloat162 ll0, ll1;
        ll0.x = __float2bfloat16(v00 - __bfloat162float(h00));
        ll0.y = __float2bfloat16(v01 - __bfloat162float(h01));
        ll1.x = __float2bfloat16(v10 - __bfloat162float(h10));
        ll1.y = __float2bfloat16(v11 - __bfloat162float(h11));
        *(__nv_bfloat162*)(row0 + d)          = hh0;
        *(__nv_bfloat162*)(row0 + KBASE + d)  = ll0;
        *(__nv_bfloat162*)(row1 + d)          = hh1;
        *(__nv_bfloat162*)(row1 + KBASE + d)  = ll1;
    }
}

// ---------------------------------------------------------------------------
// Launch
// ---------------------------------------------------------------------------
extern "C" void kernel_launch(void* const* d_in, const int* in_sizes, int n_in,
                              void* d_out, int out_size)
{
    const float* X     = (const float*)d_in[0];
    const float* W_qkv = (const float*)d_in[1];
    const float* b_qkv = (const float*)d_in[2];
    const float* W_out = (const float*)d_in[3];
    const float* b_out = (const float*)d_in[4];
    float* out = (float*)d_out;

    void *xp_p, *wq_p, *ap_p, *wo_p;
    cudaGetSymbolAddress(&xp_p, g_Xp);
    cudaGetSymbolAddress(&wq_p, g_Wqkvp);
    cudaGetSymbolAddress(&ap_p, g_attnp);
    cudaGetSymbolAddress(&wo_p, g_Woutp);
    __nv_bfloat16* Xp    = (__nv_bfloat16*)xp_p;
    __nv_bfloat16* Wqkvp = (__nv_bfloat16*)wq_p;
    __nv_bfloat16* attnp = (__nv_bfloat16*)ap_p;
    __nv_bfloat16* Woutp = (__nv_bfloat16*)wo_p;

    static bool attr_set = false;
    if (!attr_set) {
        cudaFuncSetAttribute(fa_kernel,
                             cudaFuncAttributeMaxDynamicSharedMemorySize,
                             FA_SMEM_TOTAL);
        cudaFuncSetAttribute(gemm_qkv,
                             cudaFuncAttributeMaxDynamicSharedMemorySize,
                             GEMM_SMEM);
        cudaFuncSetAttribute(gemm_mma,
                             cudaFuncAttributeMaxDynamicSharedMemorySize,
                             GEMM_SMEM);
        attr_set = true;
    }

    // 0) [hi|lo] splits of inputs (vectorized x4)
    convert_split4<<<(MROWS * D_ / 4 + 255) / 256, 256>>>(
        (const float4*)X, Xp, D_, MROWS * D_ / 4);
    convert_split4<<<(QKV_N * D_ / 4 + 255) / 256, 256>>>(
        (const float4*)W_qkv, Wqkvp, D_, QKV_N * D_ / 4);
    convert_split4<<<(D_ * D_ / 4 + 255) / 256, 256>>>(
        (const float4*)W_out, Woutp, D_, D_ * D_ / 4);

    // 1) QKV projection (fused 3-term) + Q/K/V hi-lo split (Q pre-scaled 1/8)
    {
        dim3 grid(QKV_N / BN, MROWS / BM);   // (24, 32)
        gemm_qkv<<<grid, GEMM_THREADS, GEMM_SMEM>>>(Xp, Wqkvp, b_qkv);
    }

    // 2) Tensor-core causal flash attention (64 q/CTA, 4 warps) -> attn2
    {
        dim3 grid(S_ / 64, H_, B_);          // (32, 16, 2)
        fa_kernel<<<grid, 128, FA_SMEM_TOTAL>>>(attnp);
    }

    // 3) Output projection (fused 3-term): out = attn2 . Wout2^T + b_out
    {
        dim3 grid(D_ / BN, MROWS / BM);      // (8, 32)
        gemm_mma<<<grid, GEMM_THREADS, GEMM_SMEM>>>(attnp, Woutp, b_out, out, D_);
    }
}

// round 15
// speedup vs baseline: 1.0096x; 1.0096x over previous
#include <cuda_runtime.h>
#include <cuda_bf16.h>
#include <cstdint>
#include <cstddef>
#include <math.h>

// Problem constants
#define B_  2
#define S_  2048
#define D_  1024
#define H_  16
#define HD_ 64
#define MROWS 4096
#define QKV_N 3072
#define KBASE 1024
#define KW   2048          // [hi | lo] operand width

// ---------------------------------------------------------------------------
// Device-global scratch (allocation-free)
// ---------------------------------------------------------------------------
__device__ __nv_bfloat16 g_Xp   [(size_t)MROWS * KW];        // X2     [4096,2048]
__device__ __nv_bfloat16 g_Wqkvp[(size_t)QKV_N * KW];        // Wqkv2  [3072,2048]
__device__ __nv_bfloat16 g_attnp[(size_t)MROWS * KW];        // attn2  [4096,2048]
__device__ __nv_bfloat16 g_Woutp[(size_t)D_    * KW];        // Wout2  [1024,2048]
__device__ __nv_bfloat16 g_Qp[(size_t)B_ * H_ * S_ * 128];   // [b,h,s,(hi|lo)]
__device__ __nv_bfloat16 g_Kp[(size_t)B_ * H_ * S_ * 128];
__device__ __nv_bfloat16 g_Vp[(size_t)B_ * H_ * S_ * 128];

// ---------------------------------------------------------------------------
// Helpers
// ---------------------------------------------------------------------------
__device__ __forceinline__ uint32_t s2u(const void* p) {
    uint32_t a;
    asm("{ .reg .u64 t; cvta.to.shared.u64 t, %1; cvt.u32.u64 %0, t; }"
        : "=r"(a) : "l"(p));
    return a;
}
__device__ __forceinline__ void ldmatrix_x4(uint32_t* r, uint32_t addr) {
    asm volatile("ldmatrix.sync.aligned.m8n8.x4.shared.b16 {%0,%1,%2,%3}, [%4];"
                 : "=r"(r[0]), "=r"(r[1]), "=r"(r[2]), "=r"(r[3]) : "r"(addr));
}
__device__ __forceinline__ void ldmatrix_x4_t(uint32_t* r, uint32_t addr) {
    asm volatile("ldmatrix.sync.aligned.m8n8.x4.trans.shared.b16 {%0,%1,%2,%3}, [%4];"
                 : "=r"(r[0]), "=r"(r[1]), "=r"(r[2]), "=r"(r[3]) : "r"(addr));
}
__device__ __forceinline__ void mma16816(float* c, const uint32_t* a,
                                         const uint32_t* b) {
    asm volatile(
        "mma.sync.aligned.m16n8k16.row.col.f32.bf16.bf16.f32 "
        "{%0,%1,%2,%3}, {%4,%5,%6,%7}, {%8,%9}, {%0,%1,%2,%3};"
        : "+f"(c[0]), "+f"(c[1]), "+f"(c[2]), "+f"(c[3])
        : "r"(a[0]), "r"(a[1]), "r"(a[2]), "r"(a[3]), "r"(b[0]), "r"(b[1]));
}
__device__ __forceinline__ void cp_async16(uint32_t dst, const void* src) {
    asm volatile("cp.async.cg.shared.global [%0], [%1], 16;" :: "r"(dst), "l"(src));
}
__device__ __forceinline__ uint32_t pack_bf2(float lo, float hi) {
    uint32_t d;
    asm("cvt.rn.bf16x2.f32 %0, %1, %2;" : "=r"(d) : "f"(hi), "f"(lo));
    return d;
}

// ---------------------------------------------------------------------------
// Merged fp32 -> bf16 [hi | lo] split for X, W_qkv, W_out in ONE launch.
// Segment dispatch on flattened float4 index.
// ---------------------------------------------------------------------------
#define X_T4   ((MROWS * D_) / 4)     // 1048576
#define WQ_T4  ((QKV_N * D_) / 4)     // 786432
#define WO_T4  ((D_ * D_) / 4)        // 262144
#define ALL_T4 (X_T4 + WQ_T4 + WO_T4) // 2097152

__global__ void __launch_bounds__(256)
convert_all(const float4* __restrict__ X, const float4* __restrict__ Wq,
            const float4* __restrict__ Wo)
{
    int gi = blockIdx.x * 256 + threadIdx.x;
    if (gi >= ALL_T4) return;
    const float4* src;
    __nv_bfloat16* dst;
    int i4;
    if (gi < X_T4) {
        src = X;  dst = g_Xp;    i4 = gi;
    } else if (gi < X_T4 + WQ_T4) {
        src = Wq; dst = g_Wqkvp; i4 = gi - X_T4;
    } else {
        src = Wo; dst = g_Woutp; i4 = gi - X_T4 - WQ_T4;
    }
    int idx = i4 * 4;
    int m = idx >> 10, k = idx & 1023;       // K = 1024 for all three
    float4 x = src[i4];
    uint32_t hh0 = pack_bf2(x.x, x.y);
    uint32_t hh1 = pack_bf2(x.z, x.w);
    __nv_bfloat162 h0 = *(__nv_bfloat162*)&hh0;
    __nv_bfloat162 h1 = *(__nv_bfloat162*)&hh1;
    uint32_t ll0 = pack_bf2(x.x - __bfloat162float(h0.x),
                            x.y - __bfloat162float(h0.y));
    uint32_t ll1 = pack_bf2(x.z - __bfloat162float(h1.x),
                            x.w - __bfloat162float(h1.y));
    size_t base = (size_t)m * KW + k;
    *(uint2*)&dst[base]         = make_uint2(hh0, hh1);
    *(uint2*)&dst[base + KBASE] = make_uint2(ll0, ll1);
}

// ---------------------------------------------------------------------------
// Fused error-compensated GEMM over K=1024 with [hi|lo] operands:
//   C = Ahi.Bhi^T + Ahi.Blo^T + Alo.Bhi^T   (fp32 accum)
// CTA 128x128, 4 warps (64x64 warp tile), K-chunk 16, 3-stage cp.async,
// ONE barrier per chunk, 2 CTAs/SM.
// ---------------------------------------------------------------------------
#define BM 128
#define BN 128
#define BKC 16
#define GPAD 24                                  // 16 data + 8 pad bf16
#define STAGE_BYTES (512 * GPAD * 2)             // 24576
#define GEMM_SMEM   (3 * STAGE_BYTES)            // 73728
#define GEMM_THREADS 128

struct GemmCtx {
    float acc[4][8][4];
    int mrow, ncol;
};

__device__ __forceinline__ void gemm_fused_prefetch(
    const __nv_bfloat16* __restrict__ A2, const __nv_bfloat16* __restrict__ B2,
    uint32_t sb, int koff, int tid)
{
    #pragma unroll
    for (int i = 0; i < 8; i++) {
        int g    = tid + i * GEMM_THREADS;   // 0..1023
        int row  = g >> 1;                   // 0..511
        int c8   = (g & 1) * 8;
        int part = row >> 7;                 // 0 Ahi, 1 Alo, 2 Bhi, 3 Blo
        int r    = row & 127;
        const __nv_bfloat16* base = (part < 2) ? A2 : B2;
        const __nv_bfloat16* src =
            base + (size_t)r * KW + (size_t)(part & 1) * KBASE + koff + c8;
        cp_async16(sb + (uint32_t)(row * GPAD + c8) * 2, src);
    }
}

__device__ __forceinline__ void gemm_core(
    const __nv_bfloat16* __restrict__ A2, const __nv_bfloat16* __restrict__ B2,
    int m0, int n0, uint32_t sbase, GemmCtx& ctx)
{
    const int tid  = threadIdx.x;
    const int wid  = tid >> 5;
    const int lane = tid & 31;
    const int wm   = wid & 1;
    const int wn   = wid >> 1;

    uint32_t ah_off[4], al_off[4], bh_off[4], bl_off[4];
    #pragma unroll
    for (int mi = 0; mi < 4; mi++) {
        int row = wm * 64 + mi * 16 + (lane & 15);
        int kk  = (lane >> 4) * 8;
        ah_off[mi] = (uint32_t)(row * GPAD + kk) * 2;
        al_off[mi] = (uint32_t)((128 + row) * GPAD + kk) * 2;
    }
    #pragma unroll
    for (int np = 0; np < 4; np++) {
        int row = wn * 64 + np * 16 + ((lane >> 4) << 3) + (lane & 7);
        int kk  = ((lane >> 3) & 1) * 8;
        bh_off[np] = (uint32_t)((256 + row) * GPAD + kk) * 2;
        bl_off[np] = (uint32_t)((384 + row) * GPAD + kk) * 2;
    }

    const __nv_bfloat16* Abase = A2 + (size_t)m0 * KW;
    const __nv_bfloat16* Bbase = B2 + (size_t)n0 * KW;

    #pragma unroll
    for (int i = 0; i < 4; i++)
        #pragma unroll
        for (int j = 0; j < 8; j++)
            #pragma unroll
            for (int x = 0; x < 4; x++) ctx.acc[i][j][x] = 0.f;

    const int NC = KBASE / BKC;   // 64

    gemm_fused_prefetch(Abase, Bbase, sbase, 0, tid);
    asm volatile("cp.async.commit_group;" ::: "memory");
    gemm_fused_prefetch(Abase, Bbase, sbase + STAGE_BYTES, BKC, tid);
    asm volatile("cp.async.commit_group;" ::: "memory");

    int slot = 0;
    for (int c = 0; c < NC; c++) {
        if (c + 1 < NC) {
            asm volatile("cp.async.wait_group 1;" ::: "memory");
        } else {
            asm volatile("cp.async.wait_group 0;" ::: "memory");
        }
        __syncthreads();

        if (c + 2 < NC) {
            int ps = slot + 2; if (ps >= 3) ps -= 3;
            gemm_fused_prefetch(Abase, Bbase,
                                sbase + (uint32_t)ps * STAGE_BYTES,
                                (c + 2) * BKC, tid);
            asm volatile("cp.async.commit_group;" ::: "memory");
        }

        const uint32_t scur = sbase + (uint32_t)slot * STAGE_BYTES;
        uint32_t ah[4][4], al[4][4];
        #pragma unroll
        for (int mi = 0; mi < 4; mi++) {
            ldmatrix_x4(ah[mi], scur + ah_off[mi]);
            ldmatrix_x4(al[mi], scur + al_off[mi]);
        }
        uint32_t bh[8][2], bl[8][2];
        #pragma unroll
        for (int np = 0; np < 4; np++) {
            uint32_t r[4];
            ldmatrix_x4(r, scur + bh_off[np]);
            bh[np * 2 + 0][0] = r[0]; bh[np * 2 + 0][1] = r[1];
            bh[np * 2 + 1][0] = r[2]; bh[np * 2 + 1][1] = r[3];
            ldmatrix_x4(r, scur + bl_off[np]);
            bl[np * 2 + 0][0] = r[0]; bl[np * 2 + 0][1] = r[1];
            bl[np * 2 + 1][0] = r[2]; bl[np * 2 + 1][1] = r[3];
        }
        #pragma unroll
        for (int mi = 0; mi < 4; mi++)
            #pragma unroll
            for (int ni = 0; ni < 8; ni++)
                mma16816(ctx.acc[mi][ni], ah[mi], bh[ni]);  // hi.hi
        #pragma unroll
        for (int mi = 0; mi < 4; mi++)
            #pragma unroll
            for (int ni = 0; ni < 8; ni++)
                mma16816(ctx.acc[mi][ni], ah[mi], bl[ni]);  // hi.lo
        #pragma unroll
        for (int mi = 0; mi < 4; mi++)
            #pragma unroll
            for (int ni = 0; ni < 8; ni++)
                mma16816(ctx.acc[mi][ni], al[mi], bh[ni]);  // lo.hi
        if (++slot == 3) slot = 0;
    }
    ctx.mrow = m0 + wm * 64 + (lane >> 2);
    ctx.ncol = n0 + wn * 64 + (lane & 3) * 2;
}

__global__ void __launch_bounds__(GEMM_THREADS, 2)
gemm_mma(const __nv_bfloat16* __restrict__ A2, const __nv_bfloat16* __restrict__ B2,
         const float* __restrict__ bias, float* __restrict__ C, int N)
{
    extern __shared__ __align__(16) __nv_bfloat16 gsm[];
    GemmCtx ctx;
    gemm_core(A2, B2, blockIdx.y * BM, blockIdx.x * BN, s2u(gsm), ctx);
    #pragma unroll
    for (int mi = 0; mi < 4; mi++) {
        #pragma unroll
        for (int ni = 0; ni < 8; ni++) {
            int n = ctx.ncol + ni * 8;
            float b0 = bias[n], b1 = bias[n + 1];
            int mA = ctx.mrow + mi * 16;
            float2 v0 = make_float2(ctx.acc[mi][ni][0] + b0, ctx.acc[mi][ni][1] + b1);
            float2 v1 = make_float2(ctx.acc[mi][ni][2] + b0, ctx.acc[mi][ni][3] + b1);
            *(float2*)&C[(size_t)mA * N + n]       = v0;
            *(float2*)&C[(size_t)(mA + 8) * N + n] = v1;
        }
    }
}

__device__ __forceinline__ void qkv_store(float v0, float v1, int m, int n,
                                          const float* bias) {
    v0 += bias[n]; v1 += bias[n + 1];
    int sel = n >> 10, rem = n & 1023;
    int h = rem >> 6, d = rem & 63;
    if (sel == 0) { v0 *= 0.125f; v1 *= 0.125f; }
    __nv_bfloat16* dst = (sel == 0) ? g_Qp : (sel == 1) ? g_Kp : g_Vp;
    int b = m >> 11, s = m & 2047;
    size_t idx = (((size_t)(b * H_ + h)) * S_ + s) * 128 + d;
    __nv_bfloat16 h0 = __float2bfloat16(v0), h1 = __float2bfloat16(v1);
    __nv_bfloat16 l0 = __float2bfloat16(v0 - __bfloat162float(h0));
    __nv_bfloat16 l1 = __float2bfloat16(v1 - __bfloat162float(h1));
    __nv_bfloat162 hh; hh.x = h0; hh.y = h1;
    __nv_bfloat162 ll; ll.x = l0; ll.y = l1;
    *(__nv_bfloat162*)(dst + idx)      = hh;
    *(__nv_bfloat162*)(dst + idx + 64) = ll;
}

__global__ void __launch_bounds__(GEMM_THREADS, 2)
gemm_qkv(const __nv_bfloat16* __restrict__ A2, const __nv_bfloat16* __restrict__ B2,
         const float* __restrict__ bias)
{
    extern __shared__ __align__(16) __nv_bfloat16 gsm[];
    GemmCtx ctx;
    gemm_core(A2, B2, blockIdx.y * BM, blockIdx.x * BN, s2u(gsm), ctx);
    #pragma unroll
    for (int mi = 0; mi < 4; mi++) {
        #pragma unroll
        for (int ni = 0; ni < 8; ni++) {
            int n  = ctx.ncol + ni * 8;
            int mA = ctx.mrow + mi * 16;
            qkv_store(ctx.acc[mi][ni][0], ctx.acc[mi][ni][1], mA,     n, bias);
            qkv_store(ctx.acc[mi][ni][2], ctx.acc[mi][ni][3], mA + 8, n, bias);
        }
    }
}

// ---------------------------------------------------------------------------
// Tensor-core causal flash attention: 4 warps, 64 queries/CTA (16/warp),
// KV tiles of 64 keys, cp.async double-buffered, heavy blocks first.
// NOW 3 CTAs/SM (register cap 170) — extra warps hide softmax serial gaps.
// Epilogue writes [hi|lo] attn2 rows (width 2048).
// ---------------------------------------------------------------------------
#define FA_PAD 136
#define FA_TILE_E (64 * FA_PAD)
#define FA_BUF_BYTES (2 * FA_TILE_E * 2)
#define FA_SMEM_TOTAL (2 * FA_BUF_BYTES)

__device__ __forceinline__ void fa_prefetch(uint32_t kdst, uint32_t vdst,
                                            const __nv_bfloat16* kg,
                                            const __nv_bfloat16* vg,
                                            int kt, int tid)
{
    #pragma unroll
    for (int i = 0; i < 8; i++) {
        int g = tid + i * 128;
        int r = g >> 4;
        int c = (g & 15) * 8;
        uint32_t so = (uint32_t)(r * FA_PAD + c) * 2;
        cp_async16(kdst + so, kg + (size_t)(kt + r) * 128 + c);
        cp_async16(vdst + so, vg + (size_t)(kt + r) * 128 + c);
    }
}

__global__ void __launch_bounds__(128, 3)
fa_kernel(__nv_bfloat16* __restrict__ attnp)
{
    extern __shared__ __align__(16) __nv_bfloat16 dsm[];

    const int tid  = threadIdx.x;
    const int w    = tid >> 5;
    const int lane = tid & 31;
    const int blk  = (int)gridDim.x - 1 - (int)blockIdx.x;  // heavy first
    const int h    = blockIdx.y;
    const int b    = blockIdx.z;

    const size_t bh = ((size_t)b * H_ + h) * S_;
    const __nv_bfloat16* qg = g_Qp + (bh + (size_t)blk * 64) * 128;
    const __nv_bfloat16* kg = g_Kp + bh * 128;
    const __nv_bfloat16* vg = g_Vp + bh * 128;
    const uint32_t sbase = s2u(dsm);

    for (int i = tid; i < 64 * 16; i += 128) {
        int r = i >> 4, c = (i & 15) * 8;
        *(uint4*)(dsm + r * FA_PAD + c) = *(const uint4*)(qg + r * 128 + c);
    }
    __syncthreads();
    uint32_t qa[8][4];
    {
        uint32_t base = sbase +
            (uint32_t)(((w * 16 + (lane & 15)) * FA_PAD + (lane >> 4) * 8) * 2);
        #pragma unroll
        for (int g = 0; g < 8; g++) ldmatrix_x4(qa[g], base + g * 32);
    }
    __syncthreads();

    float oa[8][4];
    #pragma unroll
    for (int i = 0; i < 8; i++)
        #pragma unroll
        for (int j = 0; j < 4; j++) oa[i][j] = 0.f;
    float m0 = -INFINITY, m1 = -INFINITY, l0 = 0.f, l1 = 0.f;

    const int qrow0  = blk * 64 + w * 16;
    const int ntiles = blk + 1;

    const uint32_t brow  = ((lane >> 4) << 3) + (lane & 7);
    const uint32_t bksel = ((lane >> 3) & 1) * 8;
    const uint32_t vrow  = ((lane >> 3) & 1) * 8 + (lane & 7);
    const uint32_t vcol  = (lane >> 4) << 3;

    fa_prefetch(sbase, sbase + FA_TILE_E * 2, kg, vg, 0, tid);
    asm volatile("cp.async.commit_group;" ::: "memory");

    for (int t = 0; t < ntiles; t++) {
        const int buf = t & 1;
        const uint32_t sKa = sbase + (uint32_t)buf * FA_BUF_BYTES;
        const uint32_t sVa = sKa + FA_TILE_E * 2;

        if (t + 1 < ntiles) {
            const uint32_t nK = sbase + (uint32_t)(buf ^ 1) * FA_BUF_BYTES;
            fa_prefetch(nK, nK + FA_TILE_E * 2, kg, vg, (t + 1) * 64, tid);
            asm volatile("cp.async.commit_group;" ::: "memory");
            asm volatile("cp.async.wait_group 1;" ::: "memory");
        } else {
            asm volatile("cp.async.wait_group 0;" ::: "memory");
        }
        __syncthreads();

        float sa[8][4];
        #pragma unroll
        for (int i = 0; i < 8; i++)
            #pragma unroll
            for (int j = 0; j < 4; j++) sa[i][j] = 0.f;

        #pragma unroll
        for (int g = 0; g < 4; g++) {
            const uint32_t kc = (uint32_t)g * 16u;
            uint32_t bf[8][2];
            #pragma unroll
            for (int np = 0; np < 4; np++) {
                uint32_t r[4];
                ldmatrix_x4(r, sKa + (uint32_t)(((np * 16 + brow) * FA_PAD) + kc + bksel) * 2);
                bf[np * 2 + 0][0] = r[0]; bf[np * 2 + 0][1] = r[1];
                bf[np * 2 + 1][0] = r[2]; bf[np * 2 + 1][1] = r[3];
            }
            #pragma unroll
            for (int nt = 0; nt < 8; nt++)
                mma16816(sa[nt], qa[g], bf[nt]);
            #pragma unroll
            for (int nt = 0; nt < 8; nt++)
                mma16816(sa[nt], qa[4 + g], bf[nt]);
        }
        #pragma unroll
        for (int g = 0; g < 4; g++) {
            const uint32_t kc = 64u + (uint32_t)g * 16u;
            uint32_t bf[8][2];
            #pragma unroll
            for (int np = 0; np < 4; np++) {
                uint32_t r[4];
                ldmatrix_x4(r, sKa + (uint32_t)(((np * 16 + brow) * FA_PAD) + kc + bksel) * 2);
                bf[np * 2 + 0][0] = r[0]; bf[np * 2 + 0][1] = r[1];
                bf[np * 2 + 1][0] = r[2]; bf[np * 2 + 1][1] = r[3];
            }
            #pragma unroll
            for (int nt = 0; nt < 8; nt++)
                mma16816(sa[nt], qa[g], bf[nt]);
        }

        if (t == ntiles - 1) {
            const int kt = t * 64;
            const int r0 = qrow0 + (lane >> 2);
            const int r1 = r0 + 8;
            #pragma unroll
            for (int nt = 0; nt < 8; nt++) {
                int c0 = kt + nt * 8 + (lane & 3) * 2;
                if (c0     > r0) sa[nt][0] = -INFINITY;
                if (c0 + 1 > r0) sa[nt][1] = -INFINITY;
                if (c0     > r1) sa[nt][2] = -INFINITY;
                if (c0 + 1 > r1) sa[nt][3] = -INFINITY;
            }
        }

        float mx0 = -INFINITY, mx1 = -INFINITY;
        #pragma unroll
        for (int nt = 0; nt < 8; nt++) {
            mx0 = fmaxf(mx0, fmaxf(sa[nt][0], sa[nt][1]));
            mx1 = fmaxf(mx1, fmaxf(sa[nt][2], sa[nt][3]));
        }
        mx0 = fmaxf(mx0, __shfl_xor_sync(0xffffffff, mx0, 1));
        mx0 = fmaxf(mx0, __shfl_xor_sync(0xffffffff, mx0, 2));
        mx1 = fmaxf(mx1, __shfl_xor_sync(0xffffffff, mx1, 1));
        mx1 = fmaxf(mx1, __shfl_xor_sync(0xffffffff, mx1, 2));
        const float m0n = fmaxf(m0, mx0);
        const float m1n = fmaxf(m1, mx1);
        const float al0 = __expf(m0 - m0n);
        const float al1 = __expf(m1 - m1n);
        m0 = m0n; m1 = m1n;

        float rs0 = 0.f, rs1 = 0.f;
        uint32_t ph[4][4], pl[4][4];
        #pragma unroll
        for (int g = 0; g < 4; g++) {
            float p00 = __expf(sa[2*g][0] - m0),   p01 = __expf(sa[2*g][1] - m0);
            float p10 = __expf(sa[2*g][2] - m1),   p11 = __expf(sa[2*g][3] - m1);
            float q00 = __expf(sa[2*g+1][0] - m0), q01 = __expf(sa[2*g+1][1] - m0);
            float q10 = __expf(sa[2*g+1][2] - m1), q11 = __expf(sa[2*g+1][3] - m1);
            rs0 += p00 + p01 + q00 + q01;
            rs1 += p10 + p11 + q10 + q11;
            ph[g][0] = pack_bf2(p00, p01);
            ph[g][1] = pack_bf2(p10, p11);
            ph[g][2] = pack_bf2(q00, q01);
            ph[g][3] = pack_bf2(q10, q11);
            float f00 = p00 - __bfloat162float(__float2bfloat16(p00));
            float f01 = p01 - __bfloat162float(__float2bfloat16(p01));
            float f10 = p10 - __bfloat162float(__float2bfloat16(p10));
            float f11 = p11 - __bfloat162float(__float2bfloat16(p11));
            float g00 = q00 - __bfloat162float(__float2bfloat16(q00));
            float g01 = q01 - __bfloat162float(__float2bfloat16(q01));
            float g10 = q10 - __bfloat162float(__float2bfloat16(q10));
            float g11 = q11 - __bfloat162float(__float2bfloat16(q11));
            pl[g][0] = pack_bf2(f00, f01);
            pl[g][1] = pack_bf2(f10, f11);
            pl[g][2] = pack_bf2(g00, g01);
            pl[g][3] = pack_bf2(g10, g11);
        }
        rs0 += __shfl_xor_sync(0xffffffff, rs0, 1);
        rs0 += __shfl_xor_sync(0xffffffff, rs0, 2);
        rs1 += __shfl_xor_sync(0xffffffff, rs1, 1);
        rs1 += __shfl_xor_sync(0xffffffff, rs1, 2);
        l0 = l0 * al0 + rs0;
        l1 = l1 * al1 + rs1;
        #pragma unroll
        for (int nt = 0; nt < 8; nt++) {
            oa[nt][0] *= al0; oa[nt][1] *= al0;
            oa[nt][2] *= al1; oa[nt][3] *= al1;
        }

        #pragma unroll
        for (int g = 0; g < 4; g++) {
            uint32_t vh[8][2], vl[8][2];
            #pragma unroll
            for (int np = 0; np < 4; np++) {
                uint32_t r[4];
                uint32_t rowa = (uint32_t)((g * 16 + vrow) * FA_PAD) * 2;
                ldmatrix_x4_t(r, sVa + rowa + (uint32_t)(np * 16 + vcol) * 2);
                vh[np * 2 + 0][0] = r[0]; vh[np * 2 + 0][1] = r[1];
                vh[np * 2 + 1][0] = r[2]; vh[np * 2 + 1][1] = r[3];
                ldmatrix_x4_t(r, sVa + rowa + (uint32_t)(64 + np * 16 + vcol) * 2);
                vl[np * 2 + 0][0] = r[0]; vl[np * 2 + 0][1] = r[1];
                vl[np * 2 + 1][0] = r[2]; vl[np * 2 + 1][1] = r[3];
            }
            #pragma unroll
            for (int nt = 0; nt < 8; nt++)
                mma16816(oa[nt], ph[g], vh[nt]);
            #pragma unroll
            for (int nt = 0; nt < 8; nt++)
                mma16816(oa[nt], pl[g], vh[nt]);
            #pragma unroll
            for (int nt = 0; nt < 8; nt++)
                mma16816(oa[nt], ph[g], vl[nt]);
        }
        __syncthreads();
    }

    const float inv0 = 1.f / l0;
    const float inv1 = 1.f / l1;
    const int s0 = qrow0 + (lane >> 2);
    __nv_bfloat16* row0 = attnp + ((size_t)b * S_ + s0) * KW + h * 64;
    __nv_bfloat16* row1 = row0 + (size_t)8 * KW;
    #pragma unroll
    for (int nt = 0; nt < 8; nt++) {
        int d = nt * 8 + (lane & 3) * 2;
        float v00 = oa[nt][0] * inv0, v01 = oa[nt][1] * inv0;
        float v10 = oa[nt][2] * inv1, v11 = oa[nt][3] * inv1;
        __nv_bfloat16 h00 = __float2bfloat16(v00), h01 = __float2bfloat16(v01);
        __nv_bfloat16 h10 = __float2bfloat16(v10), h11 = __float2bfloat16(v11);
        __nv_bfloat162 hh0; hh0.x = h00; hh0.y = h01;
        __nv_bfloat162 hh1; hh1.x = h10; hh1.y = h11;
        __nv_bfloat162 ll0, ll1;
        ll0.x = __float2bfloat16(v00 - __bfloat162float(h00));
        ll0.y = __float2bfloat16(v01 - __bfloat162float(h01));
        ll1.x = __float2bfloat16(v10 - __bfloat162float(h10));
        ll1.y = __float2bfloat16(v11 - __bfloat162float(h11));
        *(__nv_bfloat162*)(row0 + d)          = hh0;
        *(__nv_bfloat162*)(row0 + KBASE + d)  = ll0;
        *(__nv_bfloat162*)(row1 + d)          = hh1;
        *(__nv_bfloat162*)(row1 + KBASE + d)  = ll1;
    }
}

// ---------------------------------------------------------------------------
// Launch
// ---------------------------------------------------------------------------
extern "C" void kernel_launch(void* const* d_in, const int* in_sizes, int n_in,
                              void* d_out, int out_size)
{
    const float* X     = (const float*)d_in[0];
    const float* W_qkv = (const float*)d_in[1];
    const float* b_qkv = (const float*)d_in[2];
    const float* W_out = (const float*)d_in[3];
    const float* b_out = (const float*)d_in[4];
    float* out = (float*)d_out;

    void *xp_p, *wq_p, *ap_p, *wo_p;
    cudaGetSymbolAddress(&xp_p, g_Xp);
    cudaGetSymbolAddress(&wq_p, g_Wqkvp);
    cudaGetSymbolAddress(&ap_p, g_attnp);
    cudaGetSymbolAddress(&wo_p, g_Woutp);
    __nv_bfloat16* Xp    = (__nv_bfloat16*)xp_p;
    __nv_bfloat16* Wqkvp = (__nv_bfloat16*)wq_p;
    __nv_bfloat16* attnp = (__nv_bfloat16*)ap_p;
    __nv_bfloat16* Woutp = (__nv_bfloat16*)wo_p;

    static bool attr_set = false;
    if (!attr_set) {
        cudaFuncSetAttribute(fa_kernel,
                             cudaFuncAttributeMaxDynamicSharedMemorySize,
                             FA_SMEM_TOTAL);
        cudaFuncSetAttribute(gemm_qkv,
                             cudaFuncAttributeMaxDynamicSharedMemorySize,
                             GEMM_SMEM);
        cudaFuncSetAttribute(gemm_mma,
                             cudaFuncAttributeMaxDynamicSharedMemorySize,
                             GEMM_SMEM);
        attr_set = true;
    }

    // 0) [hi|lo] splits of X, W_qkv, W_out — single merged launch
    convert_all<<<(ALL_T4 + 255) / 256, 256>>>(
        (const float4*)X, (const float4*)W_qkv, (const float4*)W_out);

    // 1) QKV projection (fused 3-term) + Q/K/V hi-lo split (Q pre-scaled 1/8)
    {
        dim3 grid(QKV_N / BN, MROWS / BM);   // (24, 32)
        gemm_qkv<<<grid, GEMM_THREADS, GEMM_SMEM>>>(Xp, Wqkvp, b_qkv);
    }

    // 2) Tensor-core causal flash attention (64 q/CTA, 4 warps, 3 CTAs/SM)
    {
        dim3 grid(S_ / 64, H_, B_);          // (32, 16, 2)
        fa_kernel<<<grid, 128, FA_SMEM_TOTAL>>>(attnp);
    }

    // 3) Output projection (fused 3-term): out = attn2 . Wout2^T + b_out
    {
        dim3 grid(D_ / BN, MROWS / BM);      // (8, 32)
        gemm_mma<<<grid, GEMM_THREADS, GEMM_SMEM>>>(attnp, Woutp, b_out, out, D_);
    }
}